// round 2
// baseline (speedup 1.0000x reference)
#include <cuda_runtime.h>
#include <cuda_bf16.h>
#include <mma.h>
#include <math.h>

using namespace nvcuda;

#define BATCH 16
#define P1H 97
#define P1W 383
#define C1 32
#define P2H 47
#define P2W 190
#define C2 64
#define FLAT 571520          // 47*190*64
#define KSLICE 644
#define NSLICES 888          // ceil(FLAT / KSLICE)

// ---------------- scratch (device globals; allocations are forbidden) -------
__device__ __align__(128) __nv_bfloat16 g_x1b[(size_t)BATCH * P1H * P1W * C1]; // conv1 pooled out (bf16)
__device__ __align__(16)  __nv_bfloat16 g_w2b[288 * 64];                       // conv2 weights bf16
__device__ __align__(16)  float g_x2[(size_t)BATCH * FLAT];                    // conv2 pooled out [b][k]
__device__ float g_ypre[512 * 16];   // [n][b]
__device__ float g_zpre[256 * 16];
__device__ float g_y2[256 * 16];
__device__ float g_y3[2925 * 16];
__device__ float g_z2[128 * 16];
__device__ float g_z3[128 * 16];
__device__ float g_z4[64 * 16];
__device__ float g_z5[900 * 16];

__device__ __forceinline__ float leaky_f(float x) { return x >= 0.f ? x : 0.01f * x; }

__device__ __forceinline__ unsigned long long pack2(float a, float b) {
    unsigned long long r;
    asm("mov.b64 %0, {%1, %2};" : "=l"(r) : "f"(a), "f"(b));
    return r;
}
__device__ __forceinline__ float2 unpack2(unsigned long long v) {
    float2 r;
    asm("mov.b64 {%0, %1}, %2;" : "=f"(r.x), "=f"(r.y) : "l"(v));
    return r;
}
__device__ __forceinline__ void ffma2(unsigned long long& acc, unsigned long long a, unsigned long long b) {
#if !defined(__CUDA_ARCH__) || __CUDA_ARCH__ >= 1000
    asm("fma.rn.f32x2 %0, %1, %2, %0;" : "+l"(acc) : "l"(a), "l"(b));
#else
    float2 A = unpack2(a), B = unpack2(b), C = unpack2(acc);
    C.x = fmaf(A.x, B.x, C.x); C.y = fmaf(A.y, B.y, C.y);
    acc = pack2(C.x, C.y);
#endif
}

// ---------------- prep: conv2 weight -> bf16 ; bias-init split-K accumulators
__global__ void prep_kernel(const float* __restrict__ w2,
                            const float* __restrict__ b512,
                            const float* __restrict__ b256b) {
    int i = blockIdx.x * 256 + threadIdx.x;
    if (i < 288 * 64) g_w2b[i] = __float2bfloat16(w2[i]);
    if (i < 512 * 16) g_ypre[i] = b512[i >> 4];
    if (i < 256 * 16) g_zpre[i] = b256b[i >> 4];
}

// ---------------- conv1 (3x3, 1->32) + relu + maxpool2, fused, bf16 output --
__global__ void __launch_bounds__(256) conv1_kernel(const float* __restrict__ hidden,
                                                    const float* __restrict__ w1,
                                                    const float* __restrict__ b1) {
    __shared__ float ins[4 * 768];
    __shared__ float w1s[9 * 32];
    __shared__ float b1s[32];
    int b = blockIdx.y, ph = blockIdx.x;
    int tid = threadIdx.x;

    const float* src = hidden + ((size_t)b * 197 + 2 * ph) * 768;
    for (int i = tid; i < 4 * 768; i += 256) ins[i] = src[i];
    if (tid < 288) w1s[tid] = w1[tid];
    if (tid < 32) b1s[tid] = b1[tid];
    __syncthreads();

    int cg = tid >> 6;          // 0..3 (channel group of 8)
    int pwl = tid & 63;         // 0..63
    int c0 = cg * 8;

    float wv[9][8];
#pragma unroll
    for (int t = 0; t < 9; t++)
#pragma unroll
        for (int cc = 0; cc < 8; cc++) wv[t][cc] = w1s[t * 32 + c0 + cc];

    for (int it = 0; it < 6; it++) {
        int pw = it * 64 + pwl;
        if (pw >= 383) break;
        float in[4][4];
#pragma unroll
        for (int r = 0; r < 4; r++)
#pragma unroll
            for (int c = 0; c < 4; c++) in[r][c] = ins[r * 768 + 2 * pw + c];

        float acc[2][2][8];
#pragma unroll
        for (int i = 0; i < 2; i++)
#pragma unroll
            for (int j = 0; j < 2; j++)
#pragma unroll
                for (int cc = 0; cc < 8; cc++) acc[i][j][cc] = 0.f;

#pragma unroll
        for (int t = 0; t < 9; t++) {
            int kh = t / 3, kw = t % 3;
#pragma unroll
            for (int i = 0; i < 2; i++)
#pragma unroll
                for (int j = 0; j < 2; j++) {
                    float x = in[i + kh][j + kw];
#pragma unroll
                    for (int cc = 0; cc < 8; cc++)
                        acc[i][j][cc] = fmaf(x, wv[t][cc], acc[i][j][cc]);
                }
        }

        size_t o = (((size_t)b * P1H + ph) * P1W + pw) * C1 + c0;
        __nv_bfloat162* dst = reinterpret_cast<__nv_bfloat162*>(g_x1b + o);
#pragma unroll
        for (int t = 0; t < 4; t++) {
            int cc = 2 * t;
            float m0 = fmaxf(fmaxf(acc[0][0][cc],     acc[0][1][cc]),
                             fmaxf(acc[1][0][cc],     acc[1][1][cc]));
            float m1 = fmaxf(fmaxf(acc[0][0][cc + 1], acc[0][1][cc + 1]),
                             fmaxf(acc[1][0][cc + 1], acc[1][1][cc + 1]));
            float v0 = fmaxf(m0 + b1s[c0 + cc], 0.f);
            float v1 = fmaxf(m1 + b1s[c0 + cc + 1], 0.f);
            dst[t] = __floats2bfloat162_rn(v0, v1);
        }
    }
}

// ---------------- conv2 (3x3, 32->64) bf16 wmma implicit GEMM + relu + pool --
// CTA: batch b, pooled row ph2 (conv rows 2ph2, 2ph2+1), 32 conv cols (wt*32..)
// 8 warps: warp = (mi 0..3, nj 0..1); mi -> (conv row, 16-col half); nj -> 32 N
__global__ void __launch_bounds__(256) conv2_kernel(const float* __restrict__ b2) {
    __shared__ __align__(16) __nv_bfloat16 w2s[288 * 64];   // 36,864 B, reused as fp32 cs

    int wt = blockIdx.x;        // 0..11
    int ph2 = blockIdx.y;       // 0..46
    int b = blockIdx.z;         // 0..15
    int tid = threadIdx.x;
    int h0 = 2 * ph2;
    int w0 = wt * 32;

    // stage B (all 288x64 bf16)
    {
        uint4* d = reinterpret_cast<uint4*>(w2s);
        const uint4* s = reinterpret_cast<const uint4*>(g_w2b);
        for (int i = tid; i < 2304; i += 256) d[i] = s[i];
    }
    __syncthreads();

    int wid = tid >> 5;
    int mi = wid >> 1;          // 0..3
    int nj = wid & 1;           // 0..1
    int rowOff = mi >> 1;       // 0..1
    int wOff = (mi & 1) * 16;

    const __nv_bfloat16* aBase =
        g_x1b + (((size_t)b * P1H + (h0 + rowOff)) * P1W + (w0 + wOff)) * C1;

    wmma::fragment<wmma::matrix_a, 16, 16, 16, __nv_bfloat16, wmma::row_major> af;
    wmma::fragment<wmma::matrix_b, 16, 16, 16, __nv_bfloat16, wmma::row_major> bf;
    wmma::fragment<wmma::accumulator, 16, 16, 16, float> acc0, acc1;
    wmma::fill_fragment(acc0, 0.f);
    wmma::fill_fragment(acc1, 0.f);

    for (int kh = 0; kh < 3; kh++) {
        const __nv_bfloat16* aRow = aBase + (size_t)kh * P1W * C1;
#pragma unroll
        for (int jc = 0; jc < 6; jc++) {
            wmma::load_matrix_sync(af, aRow + jc * 16, 32);
            const __nv_bfloat16* bp = w2s + (kh * 96 + jc * 16) * 64 + nj * 32;
            wmma::load_matrix_sync(bf, bp, 64);
            wmma::mma_sync(acc0, af, bf, acc0);
            wmma::load_matrix_sync(bf, bp + 16, 64);
            wmma::mma_sync(acc1, af, bf, acc1);
        }
    }

    __syncthreads();  // everyone done reading w2s
    float* cs = reinterpret_cast<float*>(w2s);  // cs[mi][16][64] = 16 KB
    wmma::store_matrix_sync(cs + mi * 1024 + nj * 32, acc0, 64, wmma::mem_row_major);
    wmma::store_matrix_sync(cs + mi * 1024 + nj * 32 + 16, acc1, 64, wmma::mem_row_major);
    __syncthreads();

    // pooling epilogue: tid -> (pwl 0..15, 4 channels)
    int pwl = tid >> 4;
    int c0 = (tid & 15) * 4;
    int pwg = wt * 16 + pwl;
    if (pwg < P2W) {
        float4 r;
        float* rp = &r.x;
#pragma unroll
        for (int cc = 0; cc < 4; cc++) {
            int c = c0 + cc;
            float v = -1e30f;
#pragma unroll
            for (int i = 0; i < 2; i++)
#pragma unroll
                for (int j = 0; j < 2; j++) {
                    int m = 2 * pwl + j;
                    v = fmaxf(v, cs[(i * 2 + (m >> 4)) * 1024 + (m & 15) * 64 + c]);
                }
            rp[cc] = fmaxf(v + b2[c], 0.f);
        }
        size_t k = ((size_t)ph2 * P2W + pwg) * C2 + c0;
        *reinterpret_cast<float4*>(&g_x2[(size_t)b * FLAT + k]) = r;
    }
}

// ---------------- big FC: [16,FLAT] @ (w512 | w256b), split-K streaming ------
// 192 threads: tid<128 -> 4 cols of w512 ; tid>=128 -> 4 cols of w256b
__global__ void __launch_bounds__(192) fcbig_kernel(const float* __restrict__ w512,
                                                    const float* __restrict__ w256b) {
    __shared__ __align__(16) float xs[KSLICE * 18];   // [k][b] padded to 18
    int k0 = blockIdx.x * KSLICE;
    int kcount = FLAT - k0; if (kcount > KSLICE) kcount = KSLICE;
    int tid = threadIdx.x;

    for (int b = 0; b < 16; b++) {
        const float* src = g_x2 + (size_t)b * FLAT + k0;
        for (int kl = tid; kl < kcount; kl += 192)
            xs[kl * 18 + b] = src[kl];
    }
    __syncthreads();

    const float* wbase; int ncols; int col; float* obase;
    if (tid < 128) { wbase = w512;  ncols = 512; col = tid * 4;        obase = g_ypre + tid * 64; }
    else           { wbase = w256b; ncols = 256; col = (tid - 128) * 4; obase = g_zpre + (tid - 128) * 64; }
    const float4* wp = reinterpret_cast<const float4*>(wbase + (size_t)k0 * ncols + col);
    int stride4 = ncols >> 2;

    unsigned long long acc[4][8];
#pragma unroll
    for (int q = 0; q < 4; q++)
#pragma unroll
        for (int j = 0; j < 8; j++) acc[q][j] = 0ull;

    int kfull = kcount & ~7;
    for (int kl = 0; kl < kfull; kl += 8) {
#pragma unroll
        for (int u = 0; u < 8; u++) {
            float4 w4 = __ldcs(wp); wp += stride4;
            unsigned long long wa = pack2(w4.x, w4.x);
            unsigned long long wb = pack2(w4.y, w4.y);
            unsigned long long wc = pack2(w4.z, w4.z);
            unsigned long long wd = pack2(w4.w, w4.w);
            const unsigned long long* xr =
                reinterpret_cast<const unsigned long long*>(&xs[(kl + u) * 18]);
#pragma unroll
            for (int j = 0; j < 8; j++) {
                unsigned long long xv = xr[j];
                ffma2(acc[0][j], wa, xv);
                ffma2(acc[1][j], wb, xv);
                ffma2(acc[2][j], wc, xv);
                ffma2(acc[3][j], wd, xv);
            }
        }
    }
    for (int kl = kfull; kl < kcount; kl++) {
        float4 w4 = __ldcs(wp); wp += stride4;
        unsigned long long wa = pack2(w4.x, w4.x);
        unsigned long long wb = pack2(w4.y, w4.y);
        unsigned long long wc = pack2(w4.z, w4.z);
        unsigned long long wd = pack2(w4.w, w4.w);
        const unsigned long long* xr =
            reinterpret_cast<const unsigned long long*>(&xs[kl * 18]);
#pragma unroll
        for (int j = 0; j < 8; j++) {
            unsigned long long xv = xr[j];
            ffma2(acc[0][j], wa, xv);
            ffma2(acc[1][j], wb, xv);
            ffma2(acc[2][j], wc, xv);
            ffma2(acc[3][j], wd, xv);
        }
    }

#pragma unroll
    for (int q = 0; q < 4; q++)
#pragma unroll
        for (int j = 0; j < 8; j++) {
            float2 v = unpack2(acc[q][j]);
            atomicAdd(obase + q * 16 + 2 * j, v.x);
            atomicAdd(obase + q * 16 + 2 * j + 1, v.y);
        }
}

// ---------------- small FC: outPre[n2][b] = bias[n2] + sum_k leaky(inPre[k][b]) w[k][n2]
__global__ void __launch_bounds__(128) smallfc_kernel(const float* __restrict__ inPre,
                                                      const float* __restrict__ w,
                                                      const float* __restrict__ bias,
                                                      float* __restrict__ outPre,
                                                      int K, int N2) {
    __shared__ float xs[512 * 16];
    int tid = threadIdx.x;
    for (int idx = tid; idx < K * 16; idx += 128) xs[idx] = leaky_f(inPre[idx]);
    __syncthreads();

    int n2 = blockIdx.x * 128 + tid;
    if (n2 < N2) {
        float acc[16];
#pragma unroll
        for (int b = 0; b < 16; b++) acc[b] = 0.f;
        for (int k = 0; k < K; k++) {
            float wv = w[(size_t)k * N2 + n2];
#pragma unroll
            for (int b = 0; b < 16; b++) acc[b] = fmaf(wv, xs[k * 16 + b], acc[b]);
        }
        float bb = bias[n2];
#pragma unroll
        for (int b = 0; b < 16; b++) outPre[n2 * 16 + b] = acc[b] + bb;
    }
}

// ---------------- heads: softmax(leaky(y3)@wsm+bsm), sigmoid(leaky(z5)@wsig+bsig)
__global__ void heads_kernel(const float* __restrict__ wsm, const float* __restrict__ bsm,
                             const float* __restrict__ wsig, const float* __restrict__ bsig,
                             float* __restrict__ out) {
    int idx = blockIdx.x * 256 + threadIdx.x;
    if (idx < 3600) {
        int b = idx / 225, p = idx % 225;
        float yv[13];
#pragma unroll
        for (int i = 0; i < 13; i++) yv[i] = leaky_f(g_y3[(p * 13 + i) * 16 + b]);
        float l[13];
        float m = -1e30f;
#pragma unroll
        for (int o = 0; o < 13; o++) {
            float s = bsm[o];
#pragma unroll
            for (int i = 0; i < 13; i++) s = fmaf(yv[i], wsm[i * 13 + o], s);
            l[o] = s;
            m = fmaxf(m, s);
        }
        float sum = 0.f;
#pragma unroll
        for (int o = 0; o < 13; o++) { l[o] = expf(l[o] - m); sum += l[o]; }
        float inv = 1.f / sum;
        float* dst = out + (size_t)(b * 225 + p) * 13;
#pragma unroll
        for (int o = 0; o < 13; o++) dst[o] = l[o] * inv;
    } else if (idx < 7200) {
        int j = idx - 3600;
        int b = j / 225, p = j % 225;
        float zv[4];
#pragma unroll
        for (int i = 0; i < 4; i++) zv[i] = leaky_f(g_z5[(p * 4 + i) * 16 + b]);
        float* dst = out + 46800 + (size_t)(b * 225 + p) * 4;
#pragma unroll
        for (int o = 0; o < 4; o++) {
            float s = bsig[o];
#pragma unroll
            for (int i = 0; i < 4; i++) s = fmaf(zv[i], wsig[i * 4 + o], s);
            dst[o] = 1.f / (1.f + expf(-s));
        }
    }
}

// ---------------- launch ----------------------------------------------------
extern "C" void kernel_launch(void* const* d_in, const int* in_sizes, int n_in,
                              void* d_out, int out_size) {
    const float* hidden  = (const float*)d_in[0];
    const float* conv1_w = (const float*)d_in[1];
    const float* conv1_b = (const float*)d_in[2];
    const float* conv2_w = (const float*)d_in[3];
    const float* conv2_b = (const float*)d_in[4];
    const float* w512    = (const float*)d_in[5];
    const float* b512    = (const float*)d_in[6];
    const float* w256a   = (const float*)d_in[7];
    const float* b256a   = (const float*)d_in[8];
    const float* wcls    = (const float*)d_in[9];
    const float* bcls    = (const float*)d_in[10];
    const float* wsm     = (const float*)d_in[11];
    const float* bsm     = (const float*)d_in[12];
    const float* w256b   = (const float*)d_in[13];
    const float* b256b   = (const float*)d_in[14];
    const float* w128a   = (const float*)d_in[15];
    const float* b128a   = (const float*)d_in[16];
    const float* w128b   = (const float*)d_in[17];
    const float* b128b   = (const float*)d_in[18];
    const float* w64     = (const float*)d_in[19];
    const float* b64     = (const float*)d_in[20];
    const float* wreg    = (const float*)d_in[21];
    const float* breg    = (const float*)d_in[22];
    const float* wsig    = (const float*)d_in[23];
    const float* bsig    = (const float*)d_in[24];
    float* out = (float*)d_out;

    float *ypre, *zpre, *y2, *y3, *z2, *z3, *z4, *z5;
    cudaGetSymbolAddress((void**)&ypre, g_ypre);
    cudaGetSymbolAddress((void**)&zpre, g_zpre);
    cudaGetSymbolAddress((void**)&y2, g_y2);
    cudaGetSymbolAddress((void**)&y3, g_y3);
    cudaGetSymbolAddress((void**)&z2, g_z2);
    cudaGetSymbolAddress((void**)&z3, g_z3);
    cudaGetSymbolAddress((void**)&z4, g_z4);
    cudaGetSymbolAddress((void**)&z5, g_z5);

    prep_kernel<<<72, 256>>>(conv2_w, b512, b256b);
    conv1_kernel<<<dim3(P1H, BATCH), 256>>>(hidden, conv1_w, conv1_b);
    conv2_kernel<<<dim3(12, P2H, BATCH), 256>>>(conv2_b);
    fcbig_kernel<<<NSLICES, 192>>>(w512, w256b);

    smallfc_kernel<<<(256 + 127) / 128, 128>>>(ypre, w256a, b256a, y2, 512, 256);
    smallfc_kernel<<<(2925 + 127) / 128, 128>>>(y2, wcls, bcls, y3, 256, 2925);
    smallfc_kernel<<<1, 128>>>(zpre, w128a, b128a, z2, 256, 128);
    smallfc_kernel<<<1, 128>>>(z2, w128b, b128b, z3, 128, 128);
    smallfc_kernel<<<1, 128>>>(z3, w64, b64, z4, 128, 64);
    smallfc_kernel<<<(900 + 127) / 128, 128>>>(z4, wreg, breg, z5, 64, 900);

    heads_kernel<<<(7200 + 255) / 256, 256>>>(wsm, bsm, wsig, bsig, out);
}

// round 3
// speedup vs baseline: 1.1502x; 1.1502x over previous
#include <cuda_runtime.h>
#include <cuda_bf16.h>
#include <mma.h>
#include <math.h>

using namespace nvcuda;

#define BATCH 16
#define P1H 97
#define P1W 383
#define C1 32
#define P2H 47
#define P2W 190
#define C2 64
#define FLAT 571520          // 47*190*64
#define KSLICE 640           // divides FLAT exactly: 893*640 = 571520
#define NSLICES 893

// ---------------- scratch (device globals; allocations are forbidden) -------
__device__ __align__(128) float g_x1[(size_t)BATCH * P1H * P1W * C1];  // conv1 pooled out (fp32)
__device__ __align__(16)  float g_w2t[288 * 64];                       // conv2 weights tf32-rounded
__device__ __align__(16)  float g_x2[(size_t)BATCH * FLAT];            // conv2 pooled out [b][k]
__device__ float g_ypre[512 * 16];   // [n][b]
__device__ float g_zpre[256 * 16];
__device__ float g_y2[256 * 16];
__device__ float g_y3[2925 * 16];
__device__ float g_z2[128 * 16];
__device__ float g_z3[128 * 16];
__device__ float g_z4[64 * 16];
__device__ float g_z5[900 * 16];

__device__ __forceinline__ float leaky_f(float x) { return x >= 0.f ? x : 0.01f * x; }

__device__ __forceinline__ unsigned long long pack2(float a, float b) {
    unsigned long long r;
    asm("mov.b64 %0, {%1, %2};" : "=l"(r) : "f"(a), "f"(b));
    return r;
}
__device__ __forceinline__ float2 unpack2(unsigned long long v) {
    float2 r;
    asm("mov.b64 {%0, %1}, %2;" : "=f"(r.x), "=f"(r.y) : "l"(v));
    return r;
}
__device__ __forceinline__ void ffma2(unsigned long long& acc, unsigned long long a, unsigned long long b) {
    asm("fma.rn.f32x2 %0, %1, %2, %0;" : "+l"(acc) : "l"(a), "l"(b));
}

// ---------------- prep: conv2 weight -> tf32 ; bias-init split-K accumulators
__global__ void prep_kernel(const float* __restrict__ w2,
                            const float* __restrict__ b512,
                            const float* __restrict__ b256b) {
    int i = blockIdx.x * 256 + threadIdx.x;
    if (i < 288 * 64) g_w2t[i] = wmma::__float_to_tf32(w2[i]);
    if (i < 512 * 16) g_ypre[i] = b512[i >> 4];
    if (i < 256 * 16) g_zpre[i] = b256b[i >> 4];
}

// ---------------- conv1 (3x3, 1->32) + relu + maxpool2, fused, fp32 output --
__global__ void __launch_bounds__(256) conv1_kernel(const float* __restrict__ hidden,
                                                    const float* __restrict__ w1,
                                                    const float* __restrict__ b1) {
    __shared__ float ins[4 * 768];
    __shared__ float w1s[9 * 32];
    __shared__ float b1s[32];
    int b = blockIdx.y, ph = blockIdx.x;
    int tid = threadIdx.x;

    const float* src = hidden + ((size_t)b * 197 + 2 * ph) * 768;
    for (int i = tid; i < 4 * 768; i += 256) ins[i] = src[i];
    if (tid < 288) w1s[tid] = w1[tid];
    if (tid < 32) b1s[tid] = b1[tid];
    __syncthreads();

    int cg = tid >> 6;          // 0..3 (channel group of 8)
    int pwl = tid & 63;         // 0..63
    int c0 = cg * 8;

    float wv[9][8];
#pragma unroll
    for (int t = 0; t < 9; t++)
#pragma unroll
        for (int cc = 0; cc < 8; cc++) wv[t][cc] = w1s[t * 32 + c0 + cc];

    for (int it = 0; it < 6; it++) {
        int pw = it * 64 + pwl;
        if (pw >= 383) break;
        float in[4][4];
#pragma unroll
        for (int r = 0; r < 4; r++)
#pragma unroll
            for (int c = 0; c < 4; c++) in[r][c] = ins[r * 768 + 2 * pw + c];

        float acc[2][2][8];
#pragma unroll
        for (int i = 0; i < 2; i++)
#pragma unroll
            for (int j = 0; j < 2; j++)
#pragma unroll
                for (int cc = 0; cc < 8; cc++) acc[i][j][cc] = 0.f;

#pragma unroll
        for (int t = 0; t < 9; t++) {
            int kh = t / 3, kw = t % 3;
#pragma unroll
            for (int i = 0; i < 2; i++)
#pragma unroll
                for (int j = 0; j < 2; j++) {
                    float x = in[i + kh][j + kw];
#pragma unroll
                    for (int cc = 0; cc < 8; cc++)
                        acc[i][j][cc] = fmaf(x, wv[t][cc], acc[i][j][cc]);
                }
        }

        float v[8];
#pragma unroll
        for (int cc = 0; cc < 8; cc++) {
            float m = fmaxf(fmaxf(acc[0][0][cc], acc[0][1][cc]),
                            fmaxf(acc[1][0][cc], acc[1][1][cc]));
            v[cc] = fmaxf(m + b1s[c0 + cc], 0.f);
        }
        size_t o = (((size_t)b * P1H + ph) * P1W + pw) * C1 + c0;
        float4 o0 = {v[0], v[1], v[2], v[3]};
        float4 o1 = {v[4], v[5], v[6], v[7]};
        *reinterpret_cast<float4*>(g_x1 + o) = o0;
        *reinterpret_cast<float4*>(g_x1 + o + 4) = o1;
    }
}

// ---------------- conv2 (3x3, 32->64) tf32 wmma implicit GEMM + relu + pool --
// CTA: batch b, pooled-row-pair pb (conv rows 4pb..4pb+3), 32 conv cols (wt*32..)
// A staged in smem: 6 input rows x 34 cols x 32 ch fp32(tf32). B fully staged.
// 8 warps: wid -> (conv-row offset wid>>1, 16-col half (wid&1)*16); each warp all N=64.
__global__ void __launch_bounds__(256) conv2_kernel(const float* __restrict__ b2) {
    extern __shared__ float smem[];
    float* x1s = smem;          // 6*1088 = 6528 floats (26112 B)
    float* w2s = smem + 6528;   // 288*64 = 18432 floats (73728 B)

    int wt = blockIdx.x;        // 0..11
    int pb = blockIdx.y;        // 0..23
    int b = blockIdx.z;         // 0..15
    int tid = threadIdx.x;
    int h0 = 4 * pb;            // conv row base (input row base too)
    int w0 = wt * 32;

    // stage A: 6 rows x 272 uint4 (clamped at borders; clamped data feeds only
    // discarded outputs)
    for (int i = tid; i < 6 * 272; i += 256) {
        int r = i / 272, q = i - r * 272;
        int row = h0 + r; if (row > 96) row = 96;
        int col = w0 + (q >> 3); if (col > 382) col = 382;
        const float4 v = *(const float4*)(g_x1 + (((size_t)b * P1H + row) * P1W + col) * C1 + (q & 7) * 4);
        float4 o;
        o.x = wmma::__float_to_tf32(v.x);
        o.y = wmma::__float_to_tf32(v.y);
        o.z = wmma::__float_to_tf32(v.z);
        o.w = wmma::__float_to_tf32(v.w);
        *(float4*)(x1s + (size_t)r * 1088 + q * 4) = o;
    }
    // stage B (already tf32-rounded)
    {
        uint4* d = reinterpret_cast<uint4*>(w2s);
        const uint4* s = reinterpret_cast<const uint4*>(g_w2t);
        for (int i = tid; i < 4608; i += 256) d[i] = s[i];
    }
    __syncthreads();

    int wid = tid >> 5;
    int rloc = wid >> 1;            // conv-row offset 0..3
    int wOff = (wid & 1) * 16;      // col half

    wmma::fragment<wmma::matrix_a, 16, 16, 8, wmma::precision::tf32, wmma::row_major> af;
    wmma::fragment<wmma::matrix_b, 16, 16, 8, wmma::precision::tf32, wmma::row_major> bf;
    wmma::fragment<wmma::accumulator, 16, 16, 8, float> acc[4];
#pragma unroll
    for (int nf = 0; nf < 4; nf++) wmma::fill_fragment(acc[nf], 0.f);

#pragma unroll
    for (int kh = 0; kh < 3; kh++) {
        const float* ap = x1s + (rloc + kh) * 1088 + wOff * 32;
#pragma unroll
        for (int jc = 0; jc < 12; jc++) {
            wmma::load_matrix_sync(af, ap + jc * 8, 32);
            const float* bp = w2s + (kh * 96 + jc * 8) * 64;
#pragma unroll
            for (int nf = 0; nf < 4; nf++) {
                wmma::load_matrix_sync(bf, bp + nf * 16, 64);
                wmma::mma_sync(acc[nf], af, bf, acc[nf]);
            }
        }
    }

    __syncthreads();                 // B fully consumed -> reuse as C
    float* cs = w2s;                 // cs[wid][16][64] = 8192 floats
#pragma unroll
    for (int nf = 0; nf < 4; nf++)
        wmma::store_matrix_sync(cs + wid * 1024 + nf * 16, acc[nf], 64, wmma::mem_row_major);
    __syncthreads();

    // pooling epilogue: tid -> (pr 0..1, pj 0..15, 8 channels)
    int pr = tid >> 7;
    int pj = (tid >> 3) & 15;
    int c0 = (tid & 7) * 8;
    int ph2 = 2 * pb + pr;
    int pwg = wt * 16 + pj;
    if (ph2 < P2H && pwg < P2W) {
        float v[8];
#pragma unroll
        for (int cc = 0; cc < 8; cc++) {
            int c = c0 + cc;
            float m = -1e30f;
#pragma unroll
            for (int i = 0; i < 2; i++)
#pragma unroll
                for (int j = 0; j < 2; j++) {
                    int rr = 2 * pr + i;          // local conv row 0..3
                    int jj = 2 * pj + j;          // local conv col 0..31
                    m = fmaxf(m, cs[(rr * 2 + (jj >> 4)) * 1024 + (jj & 15) * 64 + c]);
                }
            v[cc] = fmaxf(m + b2[c], 0.f);
        }
        size_t o = (size_t)b * FLAT + ((size_t)ph2 * P2W + pwg) * C2 + c0;
        float4 o0 = {v[0], v[1], v[2], v[3]};
        float4 o1 = {v[4], v[5], v[6], v[7]};
        *reinterpret_cast<float4*>(g_x2 + o) = o0;
        *reinterpret_cast<float4*>(g_x2 + o + 4) = o1;
    }
}

// ---------------- big FC: [16,FLAT] @ (w512 | w256b), split-K streaming ------
// 384 threads: tid<256 -> 2 cols of w512 ; tid>=256 -> 2 cols of w256b
// 8-deep register prefetch ring keeps ~8 LDG.64 in flight per thread.
__global__ void __launch_bounds__(384, 2) fcbig_kernel(const float* __restrict__ w512,
                                                       const float* __restrict__ w256b) {
    __shared__ __align__(16) float xs[KSLICE * 18];   // [k][b], stride 18 (46080 B)
    size_t k0 = (size_t)blockIdx.x * KSLICE;
    int tid = threadIdx.x;

    for (int b = 0; b < 16; b++) {
        const float* src = g_x2 + (size_t)b * FLAT + k0;
        for (int kl = tid; kl < KSLICE; kl += 384)
            xs[kl * 18 + b] = src[kl];
    }
    __syncthreads();

    const float2* wp;
    int stride2;
    float* obase;
    if (tid < 256) {
        stride2 = 256;
        wp = reinterpret_cast<const float2*>(w512) + k0 * 256 + tid;
        obase = g_ypre + tid * 32;
    } else {
        stride2 = 128;
        wp = reinterpret_cast<const float2*>(w256b) + k0 * 128 + (tid - 256);
        obase = g_zpre + (tid - 256) * 32;
    }

    unsigned long long acc[2][8];
#pragma unroll
    for (int c = 0; c < 2; c++)
#pragma unroll
        for (int j = 0; j < 8; j++) acc[c][j] = 0ull;

    float2 w[8];
#pragma unroll
    for (int u = 0; u < 8; u++) w[u] = __ldcs(wp + (size_t)u * stride2);
    wp += (size_t)8 * stride2;

    for (int kb = 0; kb < KSLICE - 8; kb += 8) {
#pragma unroll
        for (int u = 0; u < 8; u++) {
            float2 nw = __ldcs(wp + (size_t)u * stride2);
            unsigned long long wa = pack2(w[u].x, w[u].x);
            unsigned long long wb = pack2(w[u].y, w[u].y);
            const unsigned long long* xr =
                reinterpret_cast<const unsigned long long*>(&xs[(kb + u) * 18]);
#pragma unroll
            for (int j = 0; j < 8; j++) {
                unsigned long long xv = xr[j];
                ffma2(acc[0][j], wa, xv);
                ffma2(acc[1][j], wb, xv);
            }
            w[u] = nw;
        }
        wp += (size_t)8 * stride2;
    }
#pragma unroll
    for (int u = 0; u < 8; u++) {      // final 8 rows, no prefetch
        unsigned long long wa = pack2(w[u].x, w[u].x);
        unsigned long long wb = pack2(w[u].y, w[u].y);
        const unsigned long long* xr =
            reinterpret_cast<const unsigned long long*>(&xs[(KSLICE - 8 + u) * 18]);
#pragma unroll
        for (int j = 0; j < 8; j++) {
            unsigned long long xv = xr[j];
            ffma2(acc[0][j], wa, xv);
            ffma2(acc[1][j], wb, xv);
        }
    }

#pragma unroll
    for (int c = 0; c < 2; c++)
#pragma unroll
        for (int j = 0; j < 8; j++) {
            float2 v = unpack2(acc[c][j]);
            atomicAdd(obase + c * 16 + 2 * j, v.x);
            atomicAdd(obase + c * 16 + 2 * j + 1, v.y);
        }
}

// ---------------- small FC: outPre[n2][b] = bias[n2] + sum_k leaky(inPre[k][b]) w[k][n2]
template <int K>
__global__ void __launch_bounds__(128) smallfc_kernel(const float* __restrict__ inPre,
                                                      const float* __restrict__ w,
                                                      const float* __restrict__ bias,
                                                      float* __restrict__ outPre,
                                                      int N2) {
    __shared__ float xs[K * 16];
    int tid = threadIdx.x;
    for (int idx = tid; idx < K * 16; idx += 128) xs[idx] = leaky_f(inPre[idx]);
    __syncthreads();

    int n2 = blockIdx.x * 128 + tid;
    if (n2 < N2) {
        float acc[16];
#pragma unroll
        for (int b = 0; b < 16; b++) acc[b] = 0.f;
#pragma unroll 8
        for (int k = 0; k < K; k++) {
            float wv = __ldg(w + (size_t)k * N2 + n2);
#pragma unroll
            for (int b = 0; b < 16; b++) acc[b] = fmaf(wv, xs[k * 16 + b], acc[b]);
        }
        float bb = bias[n2];
#pragma unroll
        for (int b = 0; b < 16; b++) outPre[n2 * 16 + b] = acc[b] + bb;
    }
}

// ---------------- heads: softmax(leaky(y3)@wsm+bsm), sigmoid(leaky(z5)@wsig+bsig)
__global__ void heads_kernel(const float* __restrict__ wsm, const float* __restrict__ bsm,
                             const float* __restrict__ wsig, const float* __restrict__ bsig,
                             float* __restrict__ out) {
    int idx = blockIdx.x * 256 + threadIdx.x;
    if (idx < 3600) {
        int b = idx / 225, p = idx % 225;
        float yv[13];
#pragma unroll
        for (int i = 0; i < 13; i++) yv[i] = leaky_f(g_y3[(p * 13 + i) * 16 + b]);
        float l[13];
        float m = -1e30f;
#pragma unroll
        for (int o = 0; o < 13; o++) {
            float s = bsm[o];
#pragma unroll
            for (int i = 0; i < 13; i++) s = fmaf(yv[i], wsm[i * 13 + o], s);
            l[o] = s;
            m = fmaxf(m, s);
        }
        float sum = 0.f;
#pragma unroll
        for (int o = 0; o < 13; o++) { l[o] = expf(l[o] - m); sum += l[o]; }
        float inv = 1.f / sum;
        float* dst = out + (size_t)(b * 225 + p) * 13;
#pragma unroll
        for (int o = 0; o < 13; o++) dst[o] = l[o] * inv;
    } else if (idx < 7200) {
        int j = idx - 3600;
        int b = j / 225, p = j % 225;
        float zv[4];
#pragma unroll
        for (int i = 0; i < 4; i++) zv[i] = leaky_f(g_z5[(p * 4 + i) * 16 + b]);
        float* dst = out + 46800 + (size_t)(b * 225 + p) * 4;
#pragma unroll
        for (int o = 0; o < 4; o++) {
            float s = bsig[o];
#pragma unroll
            for (int i = 0; i < 4; i++) s = fmaf(zv[i], wsig[i * 4 + o], s);
            dst[o] = 1.f / (1.f + expf(-s));
        }
    }
}

// ---------------- launch ----------------------------------------------------
extern "C" void kernel_launch(void* const* d_in, const int* in_sizes, int n_in,
                              void* d_out, int out_size) {
    const float* hidden  = (const float*)d_in[0];
    const float* conv1_w = (const float*)d_in[1];
    const float* conv1_b = (const float*)d_in[2];
    const float* conv2_w = (const float*)d_in[3];
    const float* conv2_b = (const float*)d_in[4];
    const float* w512    = (const float*)d_in[5];
    const float* b512    = (const float*)d_in[6];
    const float* w256a   = (const float*)d_in[7];
    const float* b256a   = (const float*)d_in[8];
    const float* wcls    = (const float*)d_in[9];
    const float* bcls    = (const float*)d_in[10];
    const float* wsm     = (const float*)d_in[11];
    const float* bsm     = (const float*)d_in[12];
    const float* w256b   = (const float*)d_in[13];
    const float* b256b   = (const float*)d_in[14];
    const float* w128a   = (const float*)d_in[15];
    const float* b128a   = (const float*)d_in[16];
    const float* w128b   = (const float*)d_in[17];
    const float* b128b   = (const float*)d_in[18];
    const float* w64     = (const float*)d_in[19];
    const float* b64     = (const float*)d_in[20];
    const float* wreg    = (const float*)d_in[21];
    const float* breg    = (const float*)d_in[22];
    const float* wsig    = (const float*)d_in[23];
    const float* bsig    = (const float*)d_in[24];
    float* out = (float*)d_out;

    float *ypre, *zpre, *y2, *y3, *z2, *z3, *z4, *z5;
    cudaGetSymbolAddress((void**)&ypre, g_ypre);
    cudaGetSymbolAddress((void**)&zpre, g_zpre);
    cudaGetSymbolAddress((void**)&y2, g_y2);
    cudaGetSymbolAddress((void**)&y3, g_y3);
    cudaGetSymbolAddress((void**)&z2, g_z2);
    cudaGetSymbolAddress((void**)&z3, g_z3);
    cudaGetSymbolAddress((void**)&z4, g_z4);
    cudaGetSymbolAddress((void**)&z5, g_z5);

    static bool attr_set = false;
    if (!attr_set) {
        cudaFuncSetAttribute(conv2_kernel, cudaFuncAttributeMaxDynamicSharedMemorySize, 99840);
        attr_set = true;
    }

    prep_kernel<<<72, 256>>>(conv2_w, b512, b256b);
    conv1_kernel<<<dim3(P1H, BATCH), 256>>>(hidden, conv1_w, conv1_b);
    conv2_kernel<<<dim3(12, 24, BATCH), 256, 99840>>>(conv2_b);
    fcbig_kernel<<<NSLICES, 384>>>(w512, w256b);

    smallfc_kernel<512><<<2, 128>>>(ypre, w256a, b256a, y2, 256);
    smallfc_kernel<256><<<23, 128>>>(y2, wcls, bcls, y3, 2925);
    smallfc_kernel<256><<<1, 128>>>(zpre, w128a, b128a, z2, 128);
    smallfc_kernel<128><<<1, 128>>>(z2, w128b, b128b, z3, 128);
    smallfc_kernel<128><<<1, 128>>>(z3, w64, b64, z4, 64);
    smallfc_kernel<64><<<8, 128>>>(z4, wreg, breg, z5, 900);

    heads_kernel<<<(7200 + 255) / 256, 256>>>(wsm, bsm, wsig, bsig, out);
}

// round 5
// speedup vs baseline: 1.3452x; 1.1696x over previous
#include <cuda_runtime.h>
#include <cuda_bf16.h>
#include <mma.h>
#include <math.h>

using namespace nvcuda;

#define BATCH 16
#define P1H 97
#define P1W 383
#define C1 32
#define P2H 47
#define P2W 190
#define C2 64
#define FLAT 571520          // 47*190*64
#define KSLICE 640           // 893 * 640 = 571520 exactly
#define NSLICES 893

// ---------------- scratch (device globals; allocations are forbidden) -------
__device__ __align__(128) __nv_bfloat16 g_x1b[(size_t)BATCH * P1H * P1W * C1]; // conv1 out bf16
__device__ __align__(16)  __nv_bfloat16 g_w2b[288 * 64];                       // conv2 weights bf16
__device__ __align__(16)  float g_x2[(size_t)BATCH * FLAT];                    // conv2 out [b][k]
__device__ float g_ypre[512 * 16];   // [n][b]
__device__ float g_zpre[256 * 16];
__device__ float g_y2[256 * 16];
__device__ float g_y3[2925 * 16];
__device__ float g_z4[64 * 16];
__device__ float g_z5[900 * 16];

__device__ __forceinline__ float leaky_f(float x) { return x >= 0.f ? x : 0.01f * x; }

__device__ __forceinline__ unsigned long long pack2(float a, float b) {
    unsigned long long r;
    asm("mov.b64 %0, {%1, %2};" : "=l"(r) : "f"(a), "f"(b));
    return r;
}
__device__ __forceinline__ float2 unpack2(unsigned long long v) {
    float2 r;
    asm("mov.b64 {%0, %1}, %2;" : "=f"(r.x), "=f"(r.y) : "l"(v));
    return r;
}
__device__ __forceinline__ void ffma2(unsigned long long& acc, unsigned long long a, unsigned long long b) {
    asm("fma.rn.f32x2 %0, %1, %2, %0;" : "+l"(acc) : "l"(a), "l"(b));
}

// ---------------- prep: conv2 weight -> bf16 ; bias-init split-K accumulators
__global__ void prep_kernel(const float* __restrict__ w2,
                            const float* __restrict__ b512,
                            const float* __restrict__ b256b,
                            const float* __restrict__ bcls) {
    int i = blockIdx.x * 256 + threadIdx.x;
    if (i < 288 * 64) g_w2b[i] = __float2bfloat16(w2[i]);
    if (i < 512 * 16) g_ypre[i] = b512[i >> 4];
    if (i < 256 * 16) g_zpre[i] = b256b[i >> 4];
    if (i < 2925 * 16) g_y3[i] = bcls[i >> 4];
}

// ---------------- conv1 (3x3, 1->32) + relu + maxpool2, fused, bf16 output --
__global__ void __launch_bounds__(256) conv1_kernel(const float* __restrict__ hidden,
                                                    const float* __restrict__ w1,
                                                    const float* __restrict__ b1) {
    __shared__ float ins[4 * 768];
    __shared__ float w1s[9 * 32];
    __shared__ float b1s[32];
    int b = blockIdx.y, ph = blockIdx.x;
    int tid = threadIdx.x;

    const float* src = hidden + ((size_t)b * 197 + 2 * ph) * 768;
    for (int i = tid; i < 4 * 768; i += 256) ins[i] = src[i];
    if (tid < 288) w1s[tid] = w1[tid];
    if (tid < 32) b1s[tid] = b1[tid];
    __syncthreads();

    int cg = tid >> 6;          // 0..3 (channel group of 8)
    int pwl = tid & 63;         // 0..63
    int c0 = cg * 8;

    float wv[9][8];
#pragma unroll
    for (int t = 0; t < 9; t++)
#pragma unroll
        for (int cc = 0; cc < 8; cc++) wv[t][cc] = w1s[t * 32 + c0 + cc];

    for (int it = 0; it < 6; it++) {
        int pw = it * 64 + pwl;
        if (pw >= 383) break;
        float in[4][4];
#pragma unroll
        for (int r = 0; r < 4; r++)
#pragma unroll
            for (int c = 0; c < 4; c++) in[r][c] = ins[r * 768 + 2 * pw + c];

        float acc[2][2][8];
#pragma unroll
        for (int i = 0; i < 2; i++)
#pragma unroll
            for (int j = 0; j < 2; j++)
#pragma unroll
                for (int cc = 0; cc < 8; cc++) acc[i][j][cc] = 0.f;

#pragma unroll
        for (int t = 0; t < 9; t++) {
            int kh = t / 3, kw = t % 3;
#pragma unroll
            for (int i = 0; i < 2; i++)
#pragma unroll
                for (int j = 0; j < 2; j++) {
                    float x = in[i + kh][j + kw];
#pragma unroll
                    for (int cc = 0; cc < 8; cc++)
                        acc[i][j][cc] = fmaf(x, wv[t][cc], acc[i][j][cc]);
                }
        }

        size_t o = (((size_t)b * P1H + ph) * P1W + pw) * C1 + c0;
        __nv_bfloat162* dst = reinterpret_cast<__nv_bfloat162*>(g_x1b + o);
#pragma unroll
        for (int t = 0; t < 4; t++) {
            int cc = 2 * t;
            float m0 = fmaxf(fmaxf(acc[0][0][cc],     acc[0][1][cc]),
                             fmaxf(acc[1][0][cc],     acc[1][1][cc]));
            float m1 = fmaxf(fmaxf(acc[0][0][cc + 1], acc[0][1][cc + 1]),
                             fmaxf(acc[1][0][cc + 1], acc[1][1][cc + 1]));
            dst[t] = __floats2bfloat162_rn(fmaxf(m0 + b1s[c0 + cc], 0.f),
                                           fmaxf(m1 + b1s[c0 + cc + 1], 0.f));
        }
    }
}

// ---------------- conv2 (3x3, 32->64) bf16 wmma implicit GEMM + relu + pool --
// A smem: 6 rows x (34 cols x 32 ch) bf16 contiguous. B smem: [288][72] padded
// rows (conflict-free LDSM). 8 warps: wid -> (conv-row 0..3, 16-col half).
#define CV2_BPAD 72
__global__ void __launch_bounds__(256) conv2_kernel(const float* __restrict__ b2) {
    extern __shared__ __align__(16) __nv_bfloat16 smem_h[];
    __nv_bfloat16* x1s = smem_h;                 // 6*1088 halfs = 13056 B
    __nv_bfloat16* w2s = smem_h + 6 * 1088;      // 288*72 halfs = 41472 B

    int wt = blockIdx.x;        // 0..11
    int pb = blockIdx.y;        // 0..23
    int b = blockIdx.z;         // 0..15
    int tid = threadIdx.x;
    int h0 = 4 * pb;
    int w0 = wt * 32;

    // stage A: 6 rows x 136 uint4 (border-clamped; clamped data only feeds discarded outputs)
    for (int i = tid; i < 6 * 136; i += 256) {
        int r = i / 136, q = i - r * 136;
        int row = h0 + r; if (row > 96) row = 96;
        int col = w0 + (q >> 2); if (col > 382) col = 382;
        const uint4 v = *(const uint4*)(g_x1b + (((size_t)b * P1H + row) * P1W + col) * C1 + (q & 3) * 8);
        *(uint4*)(x1s + (size_t)r * 1088 + q * 8) = v;
    }
    // stage B with row padding 64->72: 288 rows x 8 uint4 (8 halves each)
    for (int i = tid; i < 2304; i += 256) {
        int k = i >> 3, n0 = (i & 7) * 8;
        uint4 v = *(const uint4*)(g_w2b + k * 64 + n0);
        *(uint4*)(w2s + k * CV2_BPAD + n0) = v;
    }
    __syncthreads();

    int wid = tid >> 5;
    int rloc = wid >> 1;            // conv-row offset 0..3
    int wOff = (wid & 1) * 16;      // col half

    wmma::fragment<wmma::matrix_a, 16, 16, 16, __nv_bfloat16, wmma::row_major> af;
    wmma::fragment<wmma::matrix_b, 16, 16, 16, __nv_bfloat16, wmma::row_major> bf;
    wmma::fragment<wmma::accumulator, 16, 16, 16, float> acc[4];
#pragma unroll
    for (int nf = 0; nf < 4; nf++) wmma::fill_fragment(acc[nf], 0.f);

#pragma unroll
    for (int kh = 0; kh < 3; kh++) {
        const __nv_bfloat16* ap = x1s + (rloc + kh) * 1088 + wOff * 32;
#pragma unroll
        for (int jc = 0; jc < 6; jc++) {
            wmma::load_matrix_sync(af, ap + jc * 16, 32);
            const __nv_bfloat16* bp = w2s + (kh * 96 + jc * 16) * CV2_BPAD;
#pragma unroll
            for (int nf = 0; nf < 4; nf++) {
                wmma::load_matrix_sync(bf, bp + nf * 16, CV2_BPAD);
                wmma::mma_sync(acc[nf], af, bf, acc[nf]);
            }
        }
    }

    __syncthreads();                 // B fully consumed -> reuse as C (fp32)
    float* cs = reinterpret_cast<float*>(w2s);   // 8 x 1024 floats = 32 KB <= 41 KB
#pragma unroll
    for (int nf = 0; nf < 4; nf++)
        wmma::store_matrix_sync(cs + wid * 1024 + nf * 16, acc[nf], 64, wmma::mem_row_major);
    __syncthreads();

    // pooling epilogue: tid -> (pr 0..1, pj 0..15, 8 channels)
    int pr = tid >> 7;
    int pj = (tid >> 3) & 15;
    int c0 = (tid & 7) * 8;
    int ph2 = 2 * pb + pr;
    int pwg = wt * 16 + pj;
    if (ph2 < P2H && pwg < P2W) {
        float v[8];
#pragma unroll
        for (int cc = 0; cc < 8; cc++) {
            int c = c0 + cc;
            float m = -1e30f;
#pragma unroll
            for (int i = 0; i < 2; i++)
#pragma unroll
                for (int j = 0; j < 2; j++) {
                    int rr = 2 * pr + i;
                    int jj = 2 * pj + j;
                    m = fmaxf(m, cs[(rr * 2 + (jj >> 4)) * 1024 + (jj & 15) * 64 + c]);
                }
            v[cc] = fmaxf(m + b2[c], 0.f);
        }
        size_t o = (size_t)b * FLAT + ((size_t)ph2 * P2W + pwg) * C2 + c0;
        float4 o0 = {v[0], v[1], v[2], v[3]};
        float4 o1 = {v[4], v[5], v[6], v[7]};
        *reinterpret_cast<float4*>(g_x2 + o) = o0;
        *reinterpret_cast<float4*>(g_x2 + o + 4) = o1;
    }
}

// ---------------- big FC: [16,FLAT] @ (w512 | w256b), split-K streaming ------
// 192 threads x 4 cols each (LDG.128): tid<128 -> w512 float4-col tid;
// tid>=128 -> w256b float4-col tid-128. 4-deep register prefetch ring.
__global__ void __launch_bounds__(192, 3) fcbig_kernel(const float* __restrict__ w512,
                                                       const float* __restrict__ w256b) {
    __shared__ __align__(16) float xs[KSLICE * 18];   // [k][b], stride 18
    size_t k0 = (size_t)blockIdx.x * KSLICE;
    int tid = threadIdx.x;

    for (int b = 0; b < 16; b++) {
        const float* src = g_x2 + (size_t)b * FLAT + k0;
        for (int kl = tid; kl < KSLICE; kl += 192)
            xs[kl * 18 + b] = src[kl];
    }
    __syncthreads();

    const float4* wp;
    int stride4;
    float* obase;
    if (tid < 128) {
        stride4 = 128;
        wp = reinterpret_cast<const float4*>(w512) + k0 * 128 + tid;
        obase = g_ypre + tid * 64;
    } else {
        stride4 = 64;
        wp = reinterpret_cast<const float4*>(w256b) + k0 * 64 + (tid - 128);
        obase = g_zpre + (tid - 128) * 64;
    }

    unsigned long long acc[4][8];
#pragma unroll
    for (int c = 0; c < 4; c++)
#pragma unroll
        for (int j = 0; j < 8; j++) acc[c][j] = 0ull;

    float4 w[4];
#pragma unroll
    for (int u = 0; u < 4; u++) w[u] = __ldcs(wp + (size_t)u * stride4);
    wp += (size_t)4 * stride4;

    for (int kb = 0; kb < KSLICE - 4; kb += 4) {
#pragma unroll
        for (int u = 0; u < 4; u++) {
            float4 nw = __ldcs(wp + (size_t)u * stride4);
            unsigned long long wa = pack2(w[u].x, w[u].x);
            unsigned long long wb = pack2(w[u].y, w[u].y);
            unsigned long long wc = pack2(w[u].z, w[u].z);
            unsigned long long wd = pack2(w[u].w, w[u].w);
            const unsigned long long* xr =
                reinterpret_cast<const unsigned long long*>(&xs[(kb + u) * 18]);
#pragma unroll
            for (int j = 0; j < 8; j++) {
                unsigned long long xv = xr[j];
                ffma2(acc[0][j], wa, xv);
                ffma2(acc[1][j], wb, xv);
                ffma2(acc[2][j], wc, xv);
                ffma2(acc[3][j], wd, xv);
            }
            w[u] = nw;
        }
        wp += (size_t)4 * stride4;
    }
#pragma unroll
    for (int u = 0; u < 4; u++) {      // final 4 rows, no prefetch
        unsigned long long wa = pack2(w[u].x, w[u].x);
        unsigned long long wb = pack2(w[u].y, w[u].y);
        unsigned long long wc = pack2(w[u].z, w[u].z);
        unsigned long long wd = pack2(w[u].w, w[u].w);
        const unsigned long long* xr =
            reinterpret_cast<const unsigned long long*>(&xs[(KSLICE - 4 + u) * 18]);
#pragma unroll
        for (int j = 0; j < 8; j++) {
            unsigned long long xv = xr[j];
            ffma2(acc[0][j], wa, xv);
            ffma2(acc[1][j], wb, xv);
            ffma2(acc[2][j], wc, xv);
            ffma2(acc[3][j], wd, xv);
        }
    }

#pragma unroll
    for (int c = 0; c < 4; c++)
#pragma unroll
        for (int j = 0; j < 8; j++) {
            float2 v = unpack2(acc[c][j]);
            atomicAdd(obase + c * 16 + 2 * j, v.x);
            atomicAdd(obase + c * 16 + 2 * j + 1, v.y);
        }
}

// ---------------- small FC: outPre[n2][b] = bias[n2] + sum_k leaky(inPre[k][b]) w[k][n2]
template <int K>
__global__ void __launch_bounds__(128) smallfc_kernel(const float* __restrict__ inPre,
                                                      const float* __restrict__ w,
                                                      const float* __restrict__ bias,
                                                      float* __restrict__ outPre,
                                                      int N2) {
    __shared__ float xs[K * 16];
    int tid = threadIdx.x;
    for (int idx = tid; idx < K * 16; idx += 128) xs[idx] = leaky_f(inPre[idx]);
    __syncthreads();

    int n2 = blockIdx.x * 128 + tid;
    if (n2 < N2) {
        float acc[16];
#pragma unroll
        for (int b = 0; b < 16; b++) acc[b] = 0.f;
#pragma unroll 8
        for (int k = 0; k < K; k++) {
            float wv = __ldg(w + (size_t)k * N2 + n2);
#pragma unroll
            for (int b = 0; b < 16; b++) acc[b] = fmaf(wv, xs[k * 16 + b], acc[b]);
        }
        float bb = bias[n2];
#pragma unroll
        for (int b = 0; b < 16; b++) outPre[n2 * 16 + b] = acc[b] + bb;
    }
}

// ---------------- split-K small FC (K=256 in 2 halves), out pre-initialized with bias
__global__ void __launch_bounds__(128) splitfc_kernel(const float* __restrict__ inPre,
                                                      const float* __restrict__ w,
                                                      float* __restrict__ outAcc,
                                                      int N2) {
    __shared__ float xs[128 * 16];
    int tid = threadIdx.x;
    int kh = blockIdx.y;                    // 0..1 -> k in [kh*128, kh*128+128)
    const float* ip = inPre + kh * 128 * 16;
    for (int idx = tid; idx < 128 * 16; idx += 128) xs[idx] = leaky_f(ip[idx]);
    __syncthreads();

    int n2 = blockIdx.x * 128 + tid;
    if (n2 < N2) {
        float acc[16];
#pragma unroll
        for (int b = 0; b < 16; b++) acc[b] = 0.f;
        const float* wp = w + (size_t)kh * 128 * N2 + n2;
#pragma unroll 8
        for (int k = 0; k < 128; k++) {
            float wv = __ldg(wp + (size_t)k * N2);
#pragma unroll
            for (int b = 0; b < 16; b++) acc[b] = fmaf(wv, xs[k * 16 + b], acc[b]);
        }
#pragma unroll
        for (int b = 0; b < 16; b++) atomicAdd(outAcc + n2 * 16 + b, acc[b]);
    }
}

// ---------------- fused z-chain: 256 ->128 ->128 ->64, one CTA ---------------
__global__ void __launch_bounds__(128) zfused_kernel(const float* __restrict__ w128a,
                                                     const float* __restrict__ b128a,
                                                     const float* __restrict__ w128b,
                                                     const float* __restrict__ b128b,
                                                     const float* __restrict__ w64,
                                                     const float* __restrict__ b64) {
    __shared__ float xa[256 * 16];
    __shared__ float xb[128 * 16];
    int tid = threadIdx.x;
    for (int idx = tid; idx < 256 * 16; idx += 128) xa[idx] = leaky_f(g_zpre[idx]);
    __syncthreads();

    // layer 1: 256 -> 128 (store leaky into xb)
    {
        float acc[16];
#pragma unroll
        for (int b = 0; b < 16; b++) acc[b] = 0.f;
#pragma unroll 8
        for (int k = 0; k < 256; k++) {
            float wv = __ldg(w128a + (size_t)k * 128 + tid);
#pragma unroll
            for (int b = 0; b < 16; b++) acc[b] = fmaf(wv, xa[k * 16 + b], acc[b]);
        }
        float bb = b128a[tid];
#pragma unroll
        for (int b = 0; b < 16; b++) xb[tid * 16 + b] = leaky_f(acc[b] + bb);
    }
    __syncthreads();

    // layer 2: 128 -> 128 (store leaky into xa[0:2048])
    {
        float acc[16];
#pragma unroll
        for (int b = 0; b < 16; b++) acc[b] = 0.f;
#pragma unroll 8
        for (int k = 0; k < 128; k++) {
            float wv = __ldg(w128b + (size_t)k * 128 + tid);
#pragma unroll
            for (int b = 0; b < 16; b++) acc[b] = fmaf(wv, xb[k * 16 + b], acc[b]);
        }
        float bb = b128b[tid];
#pragma unroll
        for (int b = 0; b < 16; b++) xa[tid * 16 + b] = leaky_f(acc[b] + bb);
    }
    __syncthreads();

    // layer 3: 128 -> 64 (write pre-activation to g_z4)
    if (tid < 64) {
        float acc[16];
#pragma unroll
        for (int b = 0; b < 16; b++) acc[b] = 0.f;
#pragma unroll 8
        for (int k = 0; k < 128; k++) {
            float wv = __ldg(w64 + (size_t)k * 64 + tid);
#pragma unroll
            for (int b = 0; b < 16; b++) acc[b] = fmaf(wv, xa[k * 16 + b], acc[b]);
        }
        float bb = b64[tid];
#pragma unroll
        for (int b = 0; b < 16; b++) g_z4[tid * 16 + b] = acc[b] + bb;
    }
}

// ---------------- heads: softmax(leaky(y3)@wsm+bsm), sigmoid(leaky(z5)@wsig+bsig)
__global__ void heads_kernel(const float* __restrict__ wsm, const float* __restrict__ bsm,
                             const float* __restrict__ wsig, const float* __restrict__ bsig,
                             float* __restrict__ out) {
    int idx = blockIdx.x * 256 + threadIdx.x;
    if (idx < 3600) {
        int b = idx / 225, p = idx % 225;
        float yv[13];
#pragma unroll
        for (int i = 0; i < 13; i++) yv[i] = leaky_f(g_y3[(p * 13 + i) * 16 + b]);
        float l[13];
        float m = -1e30f;
#pragma unroll
        for (int o = 0; o < 13; o++) {
            float s = bsm[o];
#pragma unroll
            for (int i = 0; i < 13; i++) s = fmaf(yv[i], wsm[i * 13 + o], s);
            l[o] = s;
            m = fmaxf(m, s);
        }
        float sum = 0.f;
#pragma unroll
        for (int o = 0; o < 13; o++) { l[o] = expf(l[o] - m); sum += l[o]; }
        float inv = 1.f / sum;
        float* dst = out + (size_t)(b * 225 + p) * 13;
#pragma unroll
        for (int o = 0; o < 13; o++) dst[o] = l[o] * inv;
    } else if (idx < 7200) {
        int j = idx - 3600;
        int b = j / 225, p = j % 225;
        float zv[4];
#pragma unroll
        for (int i = 0; i < 4; i++) zv[i] = leaky_f(g_z5[(p * 4 + i) * 16 + b]);
        float* dst = out + 46800 + (size_t)(b * 225 + p) * 4;
#pragma unroll
        for (int o = 0; o < 4; o++) {
            float s = bsig[o];
#pragma unroll
            for (int i = 0; i < 4; i++) s = fmaf(zv[i], wsig[i * 4 + o], s);
            dst[o] = 1.f / (1.f + expf(-s));
        }
    }
}

// ---------------- launch ----------------------------------------------------
extern "C" void kernel_launch(void* const* d_in, const int* in_sizes, int n_in,
                              void* d_out, int out_size) {
    const float* hidden  = (const float*)d_in[0];
    const float* conv1_w = (const float*)d_in[1];
    const float* conv1_b = (const float*)d_in[2];
    const float* conv2_w = (const float*)d_in[3];
    const float* conv2_b = (const float*)d_in[4];
    const float* w512    = (const float*)d_in[5];
    const float* b512    = (const float*)d_in[6];
    const float* w256a   = (const float*)d_in[7];
    const float* b256a   = (const float*)d_in[8];
    const float* wcls    = (const float*)d_in[9];
    const float* bcls    = (const float*)d_in[10];
    const float* wsm     = (const float*)d_in[11];
    const float* bsm     = (const float*)d_in[12];
    const float* w256b   = (const float*)d_in[13];
    const float* b256b   = (const float*)d_in[14];
    const float* w128a   = (const float*)d_in[15];
    const float* b128a   = (const float*)d_in[16];
    const float* w128b   = (const float*)d_in[17];
    const float* b128b   = (const float*)d_in[18];
    const float* w64     = (const float*)d_in[19];
    const float* b64     = (const float*)d_in[20];
    const float* wreg    = (const float*)d_in[21];
    const float* breg    = (const float*)d_in[22];
    const float* wsig    = (const float*)d_in[23];
    const float* bsig    = (const float*)d_in[24];
    float* out = (float*)d_out;

    float *ypre, *y2, *y3, *z4, *z5;
    cudaGetSymbolAddress((void**)&ypre, g_ypre);
    cudaGetSymbolAddress((void**)&y2, g_y2);
    cudaGetSymbolAddress((void**)&y3, g_y3);
    cudaGetSymbolAddress((void**)&z4, g_z4);
    cudaGetSymbolAddress((void**)&z5, g_z5);

    static bool attr_set = false;
    if (!attr_set) {
        cudaFuncSetAttribute(conv2_kernel, cudaFuncAttributeMaxDynamicSharedMemorySize, 54528);
        attr_set = true;
    }

    prep_kernel<<<183, 256>>>(conv2_w, b512, b256b, bcls);
    conv1_kernel<<<dim3(P1H, BATCH), 256>>>(hidden, conv1_w, conv1_b);
    conv2_kernel<<<dim3(12, 24, BATCH), 256, 54528>>>(conv2_b);
    fcbig_kernel<<<NSLICES, 192>>>(w512, w256b);

    smallfc_kernel<512><<<2, 128>>>(ypre, w256a, b256a, y2, 256);
    splitfc_kernel<<<dim3(23, 2), 128>>>(y2, wcls, y3, 2925);
    zfused_kernel<<<1, 128>>>(w128a, b128a, w128b, b128b, w64, b64);
    smallfc_kernel<64><<<8, 128>>>(z4, wreg, breg, z5, 900);

    heads_kernel<<<29, 256>>>(wsm, bsm, wsig, bsig, out);
}

// round 6
// speedup vs baseline: 1.6585x; 1.2329x over previous
#include <cuda_runtime.h>
#include <cuda_bf16.h>
#include <mma.h>
#include <math.h>

using namespace nvcuda;

#define BATCH 16
#define P1H 97
#define P1W 383
#define C1 32
#define P2H 47
#define P2W 190
#define C2 64
#define FLAT 571520          // 47*190*64
#define KSLICE 640           // 893 * 640 = 571520 exactly
#define NSLICES 893
#define NCHUNK 80            // KSLICE / 8
#define WS_LD 772            // 768 + 4 pad (bank rotation)
#define XS_FLOATS (KSLICE * 20)
#define WS_FLOATS (8 * WS_LD)
#define FC_SMEM_BYTES ((XS_FLOATS + 2 * WS_FLOATS) * 4)

// ---------------- scratch (device globals; allocations are forbidden) -------
__device__ __align__(128) __nv_bfloat16 g_x1b[(size_t)BATCH * P1H * P1W * C1]; // conv1 out bf16
__device__ __align__(16)  __nv_bfloat16 g_w2b[288 * 64];                       // conv2 weights bf16
__device__ __align__(16)  float g_x2[(size_t)BATCH * FLAT];                    // conv2 out [b][k]
__device__ float g_ypre[512 * 16];   // [n][b]
__device__ float g_zpre[256 * 16];
__device__ float g_y2[256 * 16];
__device__ float g_y3[2925 * 16];
__device__ float g_z4[64 * 16];
__device__ float g_z5[900 * 16];

__device__ __forceinline__ float leaky_f(float x) { return x >= 0.f ? x : 0.01f * x; }

// ---------------- prep: conv2 weight -> bf16 ; bias-init split-K accumulators
__global__ void prep_kernel(const float* __restrict__ w2,
                            const float* __restrict__ b512,
                            const float* __restrict__ b256b,
                            const float* __restrict__ bcls) {
    int i = blockIdx.x * 256 + threadIdx.x;
    if (i < 288 * 64) g_w2b[i] = __float2bfloat16(w2[i]);
    if (i < 512 * 16) g_ypre[i] = b512[i >> 4];
    if (i < 256 * 16) g_zpre[i] = b256b[i >> 4];
    if (i < 2925 * 16) g_y3[i] = bcls[i >> 4];
}

// ---------------- conv1 (3x3, 1->32) + relu + maxpool2, fused, bf16 output --
__global__ void __launch_bounds__(256) conv1_kernel(const float* __restrict__ hidden,
                                                    const float* __restrict__ w1,
                                                    const float* __restrict__ b1) {
    __shared__ float ins[4 * 768];
    __shared__ float w1s[9 * 32];
    __shared__ float b1s[32];
    int b = blockIdx.y, ph = blockIdx.x;
    int tid = threadIdx.x;

    const float* src = hidden + ((size_t)b * 197 + 2 * ph) * 768;
    for (int i = tid; i < 4 * 768; i += 256) ins[i] = src[i];
    if (tid < 288) w1s[tid] = w1[tid];
    if (tid < 32) b1s[tid] = b1[tid];
    __syncthreads();

    int cg = tid >> 6;          // 0..3 (channel group of 8)
    int pwl = tid & 63;         // 0..63
    int c0 = cg * 8;

    float wv[9][8];
#pragma unroll
    for (int t = 0; t < 9; t++)
#pragma unroll
        for (int cc = 0; cc < 8; cc++) wv[t][cc] = w1s[t * 32 + c0 + cc];

    for (int it = 0; it < 6; it++) {
        int pw = it * 64 + pwl;
        if (pw >= 383) break;
        float in[4][4];
#pragma unroll
        for (int r = 0; r < 4; r++)
#pragma unroll
            for (int c = 0; c < 4; c++) in[r][c] = ins[r * 768 + 2 * pw + c];

        float acc[2][2][8];
#pragma unroll
        for (int i = 0; i < 2; i++)
#pragma unroll
            for (int j = 0; j < 2; j++)
#pragma unroll
                for (int cc = 0; cc < 8; cc++) acc[i][j][cc] = 0.f;

#pragma unroll
        for (int t = 0; t < 9; t++) {
            int kh = t / 3, kw = t % 3;
#pragma unroll
            for (int i = 0; i < 2; i++)
#pragma unroll
                for (int j = 0; j < 2; j++) {
                    float x = in[i + kh][j + kw];
#pragma unroll
                    for (int cc = 0; cc < 8; cc++)
                        acc[i][j][cc] = fmaf(x, wv[t][cc], acc[i][j][cc]);
                }
        }

        size_t o = (((size_t)b * P1H + ph) * P1W + pw) * C1 + c0;
        __nv_bfloat162* dst = reinterpret_cast<__nv_bfloat162*>(g_x1b + o);
#pragma unroll
        for (int t = 0; t < 4; t++) {
            int cc = 2 * t;
            float m0 = fmaxf(fmaxf(acc[0][0][cc],     acc[0][1][cc]),
                             fmaxf(acc[1][0][cc],     acc[1][1][cc]));
            float m1 = fmaxf(fmaxf(acc[0][0][cc + 1], acc[0][1][cc + 1]),
                             fmaxf(acc[1][0][cc + 1], acc[1][1][cc + 1]));
            dst[t] = __floats2bfloat162_rn(fmaxf(m0 + b1s[c0 + cc], 0.f),
                                           fmaxf(m1 + b1s[c0 + cc + 1], 0.f));
        }
    }
}

// ---------------- conv2 (3x3, 32->64) bf16 wmma implicit GEMM + relu + pool --
#define CV2_BPAD 72
__global__ void __launch_bounds__(256) conv2_kernel(const float* __restrict__ b2) {
    extern __shared__ __align__(16) __nv_bfloat16 smem_h[];
    __nv_bfloat16* x1s = smem_h;                 // 6*1088 halfs = 13056 B
    __nv_bfloat16* w2s = smem_h + 6 * 1088;      // 288*72 halfs = 41472 B

    int wt = blockIdx.x;        // 0..11
    int pb = blockIdx.y;        // 0..23
    int b = blockIdx.z;         // 0..15
    int tid = threadIdx.x;
    int h0 = 4 * pb;
    int w0 = wt * 32;

    // stage A: 6 rows x 136 uint4 (border-clamped; clamped data only feeds discarded outputs)
    for (int i = tid; i < 6 * 136; i += 256) {
        int r = i / 136, q = i - r * 136;
        int row = h0 + r; if (row > 96) row = 96;
        int col = w0 + (q >> 2); if (col > 382) col = 382;
        const uint4 v = *(const uint4*)(g_x1b + (((size_t)b * P1H + row) * P1W + col) * C1 + (q & 3) * 8);
        *(uint4*)(x1s + (size_t)r * 1088 + q * 8) = v;
    }
    // stage B with row padding 64->72: 288 rows x 8 uint4 (8 halves each)
    for (int i = tid; i < 2304; i += 256) {
        int k = i >> 3, n0 = (i & 7) * 8;
        uint4 v = *(const uint4*)(g_w2b + k * 64 + n0);
        *(uint4*)(w2s + k * CV2_BPAD + n0) = v;
    }
    __syncthreads();

    int wid = tid >> 5;
    int rloc = wid >> 1;            // conv-row offset 0..3
    int wOff = (wid & 1) * 16;      // col half

    wmma::fragment<wmma::matrix_a, 16, 16, 16, __nv_bfloat16, wmma::row_major> af;
    wmma::fragment<wmma::matrix_b, 16, 16, 16, __nv_bfloat16, wmma::row_major> bf;
    wmma::fragment<wmma::accumulator, 16, 16, 16, float> acc[4];
#pragma unroll
    for (int nf = 0; nf < 4; nf++) wmma::fill_fragment(acc[nf], 0.f);

#pragma unroll
    for (int kh = 0; kh < 3; kh++) {
        const __nv_bfloat16* ap = x1s + (rloc + kh) * 1088 + wOff * 32;
#pragma unroll
        for (int jc = 0; jc < 6; jc++) {
            wmma::load_matrix_sync(af, ap + jc * 16, 32);
            const __nv_bfloat16* bp = w2s + (kh * 96 + jc * 16) * CV2_BPAD;
#pragma unroll
            for (int nf = 0; nf < 4; nf++) {
                wmma::load_matrix_sync(bf, bp + nf * 16, CV2_BPAD);
                wmma::mma_sync(acc[nf], af, bf, acc[nf]);
            }
        }
    }

    __syncthreads();                 // B fully consumed -> reuse as C (fp32)
    float* cs = reinterpret_cast<float*>(w2s);   // 8 x 1024 floats = 32 KB
#pragma unroll
    for (int nf = 0; nf < 4; nf++)
        wmma::store_matrix_sync(cs + wid * 1024 + nf * 16, acc[nf], 64, wmma::mem_row_major);
    __syncthreads();

    // pooling epilogue: tid -> (pr 0..1, pj 0..15, 8 channels)
    int pr = tid >> 7;
    int pj = (tid >> 3) & 15;
    int c0 = (tid & 7) * 8;
    int ph2 = 2 * pb + pr;
    int pwg = wt * 16 + pj;
    if (ph2 < P2H && pwg < P2W) {
        float v[8];
#pragma unroll
        for (int cc = 0; cc < 8; cc++) {
            int c = c0 + cc;
            float m = -1e30f;
#pragma unroll
            for (int i = 0; i < 2; i++)
#pragma unroll
                for (int j = 0; j < 2; j++) {
                    int rr = 2 * pr + i;
                    int jj = 2 * pj + j;
                    m = fmaxf(m, cs[(rr * 2 + (jj >> 4)) * 1024 + (jj & 15) * 64 + c]);
                }
            v[cc] = fmaxf(m + b2[c], 0.f);
        }
        size_t o = (size_t)b * FLAT + ((size_t)ph2 * P2W + pwg) * C2 + c0;
        float4 o0 = {v[0], v[1], v[2], v[3]};
        float4 o1 = {v[4], v[5], v[6], v[7]};
        *reinterpret_cast<float4*>(g_x2 + o) = o0;
        *reinterpret_cast<float4*>(g_x2 + o + 4) = o1;
    }
}

// ---------------- big FC via TF32 tensor cores -------------------------------
// D[16 batch, 768 cols] += x[16, K] @ (w512 | w256b), split-K over 893 slices.
// CTA = 256 thr (8 warps), each warp owns 96 cols (6 n16 tiles). Weight chunks
// (8 k-rows x 768 cols = 24KB) stream through a double-buffered smem ring.
__device__ __forceinline__ void fc_ld_chunk(float4 v[6], const float* __restrict__ w512,
                                            const float* __restrict__ w256b,
                                            size_t kbase, int tid) {
#pragma unroll
    for (int i = 0; i < 6; i++) {
        int idx = tid + i * 256;          // 0..1535 over [8 rows][192 float4]
        int r = idx / 192;
        int c4 = idx - r * 192;
        const float* src = (c4 < 128)
            ? (w512  + (kbase + r) * 512 + c4 * 4)
            : (w256b + (kbase + r) * 256 + (c4 - 128) * 4);
        v[i] = __ldcs(reinterpret_cast<const float4*>(src));
    }
}
__device__ __forceinline__ void fc_st_chunk(float* __restrict__ buf, const float4 v[6], int tid) {
#pragma unroll
    for (int i = 0; i < 6; i++) {
        int idx = tid + i * 256;
        int r = idx / 192;
        int c4 = idx - r * 192;
        float4 o;
        o.x = wmma::__float_to_tf32(v[i].x);
        o.y = wmma::__float_to_tf32(v[i].y);
        o.z = wmma::__float_to_tf32(v[i].z);
        o.w = wmma::__float_to_tf32(v[i].w);
        *reinterpret_cast<float4*>(buf + r * WS_LD + c4 * 4) = o;
    }
}

__global__ void __launch_bounds__(256) fcbig_tf32_kernel(const float* __restrict__ w512,
                                                         const float* __restrict__ w256b) {
    extern __shared__ __align__(16) float smem_f[];
    float* xs  = smem_f;                         // [KSLICE][20] tf32 x^T
    float* ws0 = smem_f + XS_FLOATS;             // [8][WS_LD]
    float* ws1 = ws0 + WS_FLOATS;

    int tid = threadIdx.x;
    int wid = tid >> 5;
    int lane = tid & 31;
    size_t k0 = (size_t)blockIdx.x * KSLICE;

    // stage x^T slice [k][b], tf32-rounded (coalesced gmem reads per batch row)
    for (int b = 0; b < 16; b++) {
        const float* src = g_x2 + (size_t)b * FLAT + k0;
        for (int kl = tid; kl < KSLICE; kl += 256)
            xs[kl * 20 + b] = wmma::__float_to_tf32(src[kl]);
    }

    float4 v[6];
    fc_ld_chunk(v, w512, w256b, k0, tid);
    fc_st_chunk(ws0, v, tid);
    __syncthreads();

    wmma::fragment<wmma::matrix_a, 16, 16, 8, wmma::precision::tf32, wmma::col_major> af;
    wmma::fragment<wmma::matrix_b, 16, 16, 8, wmma::precision::tf32, wmma::row_major> bfr;
    wmma::fragment<wmma::accumulator, 16, 16, 8, float> acc[6];
#pragma unroll
    for (int t = 0; t < 6; t++) wmma::fill_fragment(acc[t], 0.f);

    for (int c = 0; c < NCHUNK; c++) {
        if (c + 1 < NCHUNK) fc_ld_chunk(v, w512, w256b, k0 + (size_t)(c + 1) * 8, tid);

        float* buf = (c & 1) ? ws1 : ws0;
        wmma::load_matrix_sync(af, xs + c * 160, 20);       // 8 k-rows of x^T
        const float* wb = buf + wid * 96;
#pragma unroll
        for (int t = 0; t < 6; t++) {
            wmma::load_matrix_sync(bfr, wb + t * 16, WS_LD);
            wmma::mma_sync(acc[t], af, bfr, acc[t]);
        }

        if (c + 1 < NCHUNK) fc_st_chunk(((c + 1) & 1) ? ws1 : ws0, v, tid);
        __syncthreads();
    }

    // epilogue: frag -> smem patch -> atomicAdd into bias-initialized buffers
    float* patch = ws0 + wid * 256;     // 16x16 row-major (m=batch, n=col)
#pragma unroll
    for (int t = 0; t < 6; t++) {
        wmma::store_matrix_sync(patch, acc[t], 16, wmma::mem_row_major);
        __syncwarp();
        int gcb = wid * 96 + t * 16;
#pragma unroll
        for (int u = 0; u < 8; u++) {
            int e = lane + u * 32;
            int m = e >> 4, n = e & 15;
            int gcol = gcb + n;
            float val = patch[e];
            float* dst = (gcol < 512) ? (g_ypre + gcol * 16 + m)
                                      : (g_zpre + (gcol - 512) * 16 + m);
            atomicAdd(dst, val);
        }
        __syncwarp();
    }
}

// ---------------- small FC: outPre[n2][b] = bias[n2] + sum_k leaky(inPre[k][b]) w[k][n2]
template <int K>
__global__ void __launch_bounds__(128) smallfc_kernel(const float* __restrict__ inPre,
                                                      const float* __restrict__ w,
                                                      const float* __restrict__ bias,
                                                      float* __restrict__ outPre,
                                                      int N2) {
    __shared__ float xs[K * 16];
    int tid = threadIdx.x;
    for (int idx = tid; idx < K * 16; idx += 128) xs[idx] = leaky_f(inPre[idx]);
    __syncthreads();

    int n2 = blockIdx.x * 128 + tid;
    if (n2 < N2) {
        float acc[16];
#pragma unroll
        for (int b = 0; b < 16; b++) acc[b] = 0.f;
#pragma unroll 8
        for (int k = 0; k < K; k++) {
            float wv = __ldg(w + (size_t)k * N2 + n2);
#pragma unroll
            for (int b = 0; b < 16; b++) acc[b] = fmaf(wv, xs[k * 16 + b], acc[b]);
        }
        float bb = bias[n2];
#pragma unroll
        for (int b = 0; b < 16; b++) outPre[n2 * 16 + b] = acc[b] + bb;
    }
}

// ---------------- split-K small FC (K=256 in 2 halves), out pre-initialized with bias
__global__ void __launch_bounds__(128) splitfc_kernel(const float* __restrict__ inPre,
                                                      const float* __restrict__ w,
                                                      float* __restrict__ outAcc,
                                                      int N2) {
    __shared__ float xs[128 * 16];
    int tid = threadIdx.x;
    int kh = blockIdx.y;                    // 0..1 -> k in [kh*128, kh*128+128)
    const float* ip = inPre + kh * 128 * 16;
    for (int idx = tid; idx < 128 * 16; idx += 128) xs[idx] = leaky_f(ip[idx]);
    __syncthreads();

    int n2 = blockIdx.x * 128 + tid;
    if (n2 < N2) {
        float acc[16];
#pragma unroll
        for (int b = 0; b < 16; b++) acc[b] = 0.f;
        const float* wp = w + (size_t)kh * 128 * N2 + n2;
#pragma unroll 8
        for (int k = 0; k < 128; k++) {
            float wv = __ldg(wp + (size_t)k * N2);
#pragma unroll
            for (int b = 0; b < 16; b++) acc[b] = fmaf(wv, xs[k * 16 + b], acc[b]);
        }
#pragma unroll
        for (int b = 0; b < 16; b++) atomicAdd(outAcc + n2 * 16 + b, acc[b]);
    }
}

// ---------------- fused z-chain: 256 ->128 ->128 ->64, one CTA ---------------
__global__ void __launch_bounds__(128) zfused_kernel(const float* __restrict__ w128a,
                                                     const float* __restrict__ b128a,
                                                     const float* __restrict__ w128b,
                                                     const float* __restrict__ b128b,
                                                     const float* __restrict__ w64,
                                                     const float* __restrict__ b64) {
    __shared__ float xa[256 * 16];
    __shared__ float xb[128 * 16];
    int tid = threadIdx.x;
    for (int idx = tid; idx < 256 * 16; idx += 128) xa[idx] = leaky_f(g_zpre[idx]);
    __syncthreads();

    {
        float acc[16];
#pragma unroll
        for (int b = 0; b < 16; b++) acc[b] = 0.f;
#pragma unroll 8
        for (int k = 0; k < 256; k++) {
            float wv = __ldg(w128a + (size_t)k * 128 + tid);
#pragma unroll
            for (int b = 0; b < 16; b++) acc[b] = fmaf(wv, xa[k * 16 + b], acc[b]);
        }
        float bb = b128a[tid];
#pragma unroll
        for (int b = 0; b < 16; b++) xb[tid * 16 + b] = leaky_f(acc[b] + bb);
    }
    __syncthreads();

    {
        float acc[16];
#pragma unroll
        for (int b = 0; b < 16; b++) acc[b] = 0.f;
#pragma unroll 8
        for (int k = 0; k < 128; k++) {
            float wv = __ldg(w128b + (size_t)k * 128 + tid);
#pragma unroll
            for (int b = 0; b < 16; b++) acc[b] = fmaf(wv, xb[k * 16 + b], acc[b]);
        }
        float bb = b128b[tid];
#pragma unroll
        for (int b = 0; b < 16; b++) xa[tid * 16 + b] = leaky_f(acc[b] + bb);
    }
    __syncthreads();

    if (tid < 64) {
        float acc[16];
#pragma unroll
        for (int b = 0; b < 16; b++) acc[b] = 0.f;
#pragma unroll 8
        for (int k = 0; k < 128; k++) {
            float wv = __ldg(w64 + (size_t)k * 64 + tid);
#pragma unroll
            for (int b = 0; b < 16; b++) acc[b] = fmaf(wv, xa[k * 16 + b], acc[b]);
        }
        float bb = b64[tid];
#pragma unroll
        for (int b = 0; b < 16; b++) g_z4[tid * 16 + b] = acc[b] + bb;
    }
}

// ---------------- heads: softmax(leaky(y3)@wsm+bsm), sigmoid(leaky(z5)@wsig+bsig)
__global__ void heads_kernel(const float* __restrict__ wsm, const float* __restrict__ bsm,
                             const float* __restrict__ wsig, const float* __restrict__ bsig,
                             float* __restrict__ out) {
    int idx = blockIdx.x * 256 + threadIdx.x;
    if (idx < 3600) {
        int b = idx / 225, p = idx % 225;
        float yv[13];
#pragma unroll
        for (int i = 0; i < 13; i++) yv[i] = leaky_f(g_y3[(p * 13 + i) * 16 + b]);
        float l[13];
        float m = -1e30f;
#pragma unroll
        for (int o = 0; o < 13; o++) {
            float s = bsm[o];
#pragma unroll
            for (int i = 0; i < 13; i++) s = fmaf(yv[i], wsm[i * 13 + o], s);
            l[o] = s;
            m = fmaxf(m, s);
        }
        float sum = 0.f;
#pragma unroll
        for (int o = 0; o < 13; o++) { l[o] = expf(l[o] - m); sum += l[o]; }
        float inv = 1.f / sum;
        float* dst = out + (size_t)(b * 225 + p) * 13;
#pragma unroll
        for (int o = 0; o < 13; o++) dst[o] = l[o] * inv;
    } else if (idx < 7200) {
        int j = idx - 3600;
        int b = j / 225, p = j % 225;
        float zv[4];
#pragma unroll
        for (int i = 0; i < 4; i++) zv[i] = leaky_f(g_z5[(p * 4 + i) * 16 + b]);
        float* dst = out + 46800 + (size_t)(b * 225 + p) * 4;
#pragma unroll
        for (int o = 0; o < 4; o++) {
            float s = bsig[o];
#pragma unroll
            for (int i = 0; i < 4; i++) s = fmaf(zv[i], wsig[i * 4 + o], s);
            dst[o] = 1.f / (1.f + expf(-s));
        }
    }
}

// ---------------- launch ----------------------------------------------------
extern "C" void kernel_launch(void* const* d_in, const int* in_sizes, int n_in,
                              void* d_out, int out_size) {
    const float* hidden  = (const float*)d_in[0];
    const float* conv1_w = (const float*)d_in[1];
    const float* conv1_b = (const float*)d_in[2];
    const float* conv2_w = (const float*)d_in[3];
    const float* conv2_b = (const float*)d_in[4];
    const float* w512    = (const float*)d_in[5];
    const float* b512    = (const float*)d_in[6];
    const float* w256a   = (const float*)d_in[7];
    const float* b256a   = (const float*)d_in[8];
    const float* wcls    = (const float*)d_in[9];
    const float* bcls    = (const float*)d_in[10];
    const float* wsm     = (const float*)d_in[11];
    const float* bsm     = (const float*)d_in[12];
    const float* w256b   = (const float*)d_in[13];
    const float* b256b   = (const float*)d_in[14];
    const float* w128a   = (const float*)d_in[15];
    const float* b128a   = (const float*)d_in[16];
    const float* w128b   = (const float*)d_in[17];
    const float* b128b   = (const float*)d_in[18];
    const float* w64     = (const float*)d_in[19];
    const float* b64     = (const float*)d_in[20];
    const float* wreg    = (const float*)d_in[21];
    const float* breg    = (const float*)d_in[22];
    const float* wsig    = (const float*)d_in[23];
    const float* bsig    = (const float*)d_in[24];
    float* out = (float*)d_out;

    float *ypre, *y2, *y3, *z4, *z5;
    cudaGetSymbolAddress((void**)&ypre, g_ypre);
    cudaGetSymbolAddress((void**)&y2, g_y2);
    cudaGetSymbolAddress((void**)&y3, g_y3);
    cudaGetSymbolAddress((void**)&z4, g_z4);
    cudaGetSymbolAddress((void**)&z5, g_z5);

    static bool attr_set = false;
    if (!attr_set) {
        cudaFuncSetAttribute(conv2_kernel, cudaFuncAttributeMaxDynamicSharedMemorySize, 54528);
        cudaFuncSetAttribute(fcbig_tf32_kernel, cudaFuncAttributeMaxDynamicSharedMemorySize, FC_SMEM_BYTES);
        attr_set = true;
    }

    prep_kernel<<<183, 256>>>(conv2_w, b512, b256b, bcls);
    conv1_kernel<<<dim3(P1H, BATCH), 256>>>(hidden, conv1_w, conv1_b);
    conv2_kernel<<<dim3(12, 24, BATCH), 256, 54528>>>(conv2_b);
    fcbig_tf32_kernel<<<NSLICES, 256, FC_SMEM_BYTES>>>(w512, w256b);

    smallfc_kernel<512><<<2, 128>>>(ypre, w256a, b256a, y2, 256);
    splitfc_kernel<<<dim3(23, 2), 128>>>(y2, wcls, y3, 2925);
    zfused_kernel<<<1, 128>>>(w128a, b128a, w128b, b128b, w64, b64);
    smallfc_kernel<64><<<8, 128>>>(z4, wreg, breg, z5, 900);

    heads_kernel<<<29, 256>>>(wsm, bsm, wsig, bsig, out);
}